// round 15
// baseline (speedup 1.0000x reference)
#include <cuda_runtime.h>
#include <cuda_bf16.h>
#include <cuda_fp16.h>

#define NN 50000
#define NE 1600000
#define D  128
#define OD 64
#define NL 3
#define NBLK 196   // ceil(NN/256)

// ---------------- device scratch ----------------
__device__ __half g_hh[NN * D];        // node features (fp16)
__device__ float g_x[NN * D];          // MLP hidden pre-BN (fp32)
__device__ float g_xin[NN * D];        // (1+eps)h + agg (fp32)
__device__ float g_stats[NL][2 * D];   // per-layer per-channel sum & sumsq

// Pre-split weights, smem image layout:
// [layer][chunk(8)][hi/lo(2)][n(128)][kpair(8)]  (each uint = 2 bf16, low = even k)
__device__ unsigned g_w1p[NL][8][2][128][8];
__device__ unsigned g_w2p[NL][8][2][128][8];
// Wout in fp16, smem image: [chunk(8)][n(64)][kpair(8)]
__device__ unsigned g_w3p[8][64][8];

// CSR (dual-bucket counters/cursors).
// INVARIANT: g_cnt == 0 at kernel_launch entry (static zero-init on first
// call; csr_fill re-zeroes for subsequent calls).
__device__ int g_cnt[2][NN];
__device__ int g_cur[2][NN];
__device__ int g_off[NN + 1];
__device__ int g_csrc[NE];
__device__ int g_bsum[NBLK + 1];

__device__ __forceinline__ unsigned pack_bf2(float a, float b) {
    __nv_bfloat162 t = __floats2bfloat162_rn(a, b);
    return *reinterpret_cast<unsigned*>(&t);
}
__device__ __forceinline__ unsigned pack_h2(float a, float b) {
    __half2 t = __floats2half2_rn(a, b);
    return *reinterpret_cast<unsigned*>(&t);
}
__device__ __forceinline__ float bf_hi(float x) {
    return __bfloat162float(__float2bfloat16_rn(x));
}
__device__ __forceinline__ float4 h4_to_f4(uint2 u) {
    __half2 a = *reinterpret_cast<__half2*>(&u.x);
    __half2 b = *reinterpret_cast<__half2*>(&u.y);
    float2 fa = __half22float2(a), fb = __half22float2(b);
    return make_float4(fa.x, fa.y, fb.x, fb.y);
}
// accumulate 8 fp16 channels (uint4) into acc[8]
__device__ __forceinline__ void acc8(float* acc, uint4 u) {
    __half2 h0 = *reinterpret_cast<__half2*>(&u.x);
    __half2 h1 = *reinterpret_cast<__half2*>(&u.y);
    __half2 h2 = *reinterpret_cast<__half2*>(&u.z);
    __half2 h3 = *reinterpret_cast<__half2*>(&u.w);
    float2 f0 = __half22float2(h0), f1 = __half22float2(h1);
    float2 f2 = __half22float2(h2), f3 = __half22float2(h3);
    acc[0] += f0.x; acc[1] += f0.y;
    acc[2] += f1.x; acc[3] += f1.y;
    acc[4] += f2.x; acc[5] += f2.y;
    acc[6] += f3.x; acc[7] += f3.y;
}

__device__ __forceinline__ void mma_bf16(float* d, const unsigned* a,
                                         unsigned b0, unsigned b1) {
    asm volatile(
        "mma.sync.aligned.m16n8k16.row.col.f32.bf16.bf16.f32 "
        "{%0,%1,%2,%3}, {%4,%5,%6,%7}, {%8,%9}, {%0,%1,%2,%3};"
        : "+f"(d[0]), "+f"(d[1]), "+f"(d[2]), "+f"(d[3])
        : "r"(a[0]), "r"(a[1]), "r"(a[2]), "r"(a[3]), "r"(b0), "r"(b1));
}
__device__ __forceinline__ void mma_f16(float* d, const unsigned* a,
                                        unsigned b0, unsigned b1) {
    asm volatile(
        "mma.sync.aligned.m16n8k16.row.col.f32.f16.f16.f32 "
        "{%0,%1,%2,%3}, {%4,%5,%6,%7}, {%8,%9}, {%0,%1,%2,%3};"
        : "+f"(d[0]), "+f"(d[1]), "+f"(d[2]), "+f"(d[3])
        : "r"(a[0]), "r"(a[1]), "r"(a[2]), "r"(a[3]), "r"(b0), "r"(b1));
}

__device__ __forceinline__ void split4(float4 v, unsigned* hi, unsigned* lo) {
    float h0 = bf_hi(v.x), h1 = bf_hi(v.y), h2 = bf_hi(v.z), h3 = bf_hi(v.w);
    hi[0] = pack_bf2(h0, h1);
    hi[1] = pack_bf2(h2, h3);
    lo[0] = pack_bf2(v.x - h0, v.y - h1);
    lo[1] = pack_bf2(v.z - h2, v.w - h3);
}

// ---------------- fused init + histogram ----------------
#define R_HI   (NE / 4)              // 400,000
#define R_NF   (NN * D / 4)          // 1,600,000
#define R_W    (NL * 64 * 128)       // 24,576
#define R_W3   (64 * 64)             // 4,096
#define R_ST   (NL * 2 * D)          // 768
#define R_TOT  (R_HI + R_NF + R_W + R_W3 + R_ST + 1)

__global__ void init_kernel(const float* __restrict__ nf,
                            const float* __restrict__ W1,
                            const float* __restrict__ W2,
                            const float* __restrict__ Wout,
                            const int* __restrict__ dst) {
    int i = blockIdx.x * blockDim.x + threadIdx.x;
    if (i < R_HI) {
        int b = (i < NE / 8) ? 0 : 1;
        int4 d = __ldg((const int4*)dst + i);
        atomicAdd(&g_cnt[b][d.x], 1);
        atomicAdd(&g_cnt[b][d.y], 1);
        atomicAdd(&g_cnt[b][d.z], 1);
        atomicAdd(&g_cnt[b][d.w], 1);
        return;
    }
    int r = i - R_HI;
    if (r < R_NF) {
        float4 v = __ldg((const float4*)nf + r);
        __half2* p = (__half2*)g_hh + r * 2;
        p[0] = __floats2half2_rn(v.x, v.y);
        p[1] = __floats2half2_rn(v.z, v.w);
        return;
    }
    r -= R_NF;
    if (r < R_W) {
        int n = r & 127;
        int kp = (r >> 7) & 63;
        int l = r >> 13;
        int k0 = kp * 2;
        int chunk = k0 >> 4;
        int kpi = (k0 & 15) >> 1;
        {
            float w0 = __ldg(W1 + (size_t)l * D * D + k0 * D + n);
            float w1 = __ldg(W1 + (size_t)l * D * D + (k0 + 1) * D + n);
            float h0 = bf_hi(w0), h1 = bf_hi(w1);
            g_w1p[l][chunk][0][n][kpi] = pack_bf2(h0, h1);
            g_w1p[l][chunk][1][n][kpi] = pack_bf2(w0 - h0, w1 - h1);
        }
        {
            float w0 = __ldg(W2 + (size_t)l * D * D + k0 * D + n);
            float w1 = __ldg(W2 + (size_t)l * D * D + (k0 + 1) * D + n);
            float h0 = bf_hi(w0), h1 = bf_hi(w1);
            g_w2p[l][chunk][0][n][kpi] = pack_bf2(h0, h1);
            g_w2p[l][chunk][1][n][kpi] = pack_bf2(w0 - h0, w1 - h1);
        }
        return;
    }
    r -= R_W;
    if (r < R_W3) {
        int n = r & 63;
        int kp = r >> 6;
        int k0 = kp * 2;
        int chunk = k0 >> 4;
        int kpi = (k0 & 15) >> 1;
        float w0 = __ldg(Wout + k0 * OD + n);
        float w1 = __ldg(Wout + (k0 + 1) * OD + n);
        g_w3p[chunk][n][kpi] = pack_h2(w0, w1);
        return;
    }
    r -= R_W3;
    if (r < R_ST) { ((float*)g_stats)[r] = 0.f; return; }
    r -= R_ST;
    if (r == 0) g_off[0] = 0;
}

// --- hierarchical scan (3 kernels) ---
__global__ void scan1_kernel() {
    int b = blockIdx.x, tid = threadIdx.x;
    int i = b * 256 + tid;
    int c0 = (i < NN) ? g_cnt[0][i] : 0;
    int c1 = (i < NN) ? g_cnt[1][i] : 0;
    int v = c0 + c1;
    int lane = tid & 31, w = tid >> 5;
    int x = v;
#pragma unroll
    for (int o = 1; o < 32; o <<= 1) {
        int t = __shfl_up_sync(0xffffffffu, x, o);
        if (lane >= o) x += t;
    }
    __shared__ int wsum[8];
    if (lane == 31) wsum[w] = x;
    __syncthreads();
    if (w == 0 && lane < 8) {
        int y = wsum[lane];
#pragma unroll
        for (int o = 1; o < 8; o <<= 1) {
            int t = __shfl_up_sync(0xffu, y, o);
            if (lane >= o) y += t;
        }
        wsum[lane] = y;
    }
    __syncthreads();
    int incl = x + (w > 0 ? wsum[w - 1] : 0);
    if (i < NN) {
        g_off[i + 1] = incl;
        g_cur[0][i] = incl - v;
        g_cur[1][i] = incl - v + c0;
    }
    if (tid == 255) g_bsum[b] = incl;
}

__global__ void scan2_kernel() {
    int tid = threadIdx.x;
    int lane = tid & 31, w = tid >> 5;
    int v = (tid < NBLK) ? g_bsum[tid] : 0;
    int x = v;
#pragma unroll
    for (int o = 1; o < 32; o <<= 1) {
        int t = __shfl_up_sync(0xffffffffu, x, o);
        if (lane >= o) x += t;
    }
    __shared__ int wsum[8];
    if (lane == 31) wsum[w] = x;
    __syncthreads();
    if (w == 0 && lane < 8) {
        int y = wsum[lane];
#pragma unroll
        for (int o = 1; o < 8; o <<= 1) {
            int t = __shfl_up_sync(0xffu, y, o);
            if (lane >= o) y += t;
        }
        wsum[lane] = y;
    }
    __syncthreads();
    int incl = x + (w > 0 ? wsum[w - 1] : 0);
    if (tid < NBLK) g_bsum[tid] = incl - v;
}

__global__ void scan3_kernel() {
    int b = blockIdx.x;
    int i = b * 256 + threadIdx.x;
    if (i < NN) {
        int base = g_bsum[b];
        g_off[i + 1] += base;
        g_cur[0][i] += base;
        g_cur[1][i] += base;
    }
}

// fill + re-zero g_cnt for the NEXT call
__global__ void csr_fill_kernel(const int* __restrict__ src,
                                const int* __restrict__ dst) {
    int i = blockIdx.x * blockDim.x + threadIdx.x;
    if (i < NN) { g_cnt[0][i] = 0; g_cnt[1][i] = 0; }
    if (i >= NE / 4) return;
    int b = (i < NE / 8) ? 0 : 1;
    int4 s = __ldg((const int4*)src + i);
    int4 d = __ldg((const int4*)dst + i);
    int p0 = atomicAdd(&g_cur[b][d.x], 1);
    int p1 = atomicAdd(&g_cur[b][d.y], 1);
    int p2 = atomicAdd(&g_cur[b][d.z], 1);
    int p3 = atomicAdd(&g_cur[b][d.w], 1);
    g_csrc[p0] = s.x;
    g_csrc[p1] = s.y;
    g_csrc[p2] = s.z;
    g_csrc[p3] = s.w;
}

// ---------------- gather (fp16 h, half-warp-per-row uint4 loads) ----------------
// Lanes 0-15 process even-indexed neighbors, lanes 16-31 odd-indexed; each lane
// loads uint4 (8 channels, 16B) -> 2 rows per load instruction across the warp,
// half the issue count of the uint2 scheme. Halves combined via shfl_xor(16).
__global__ void __launch_bounds__(256) gather_kernel(const float* __restrict__ eps,
                                                     int layer) {
    int node = blockIdx.x * 8 + (threadIdx.x >> 5);
    if (node >= NN) return;
    int lane = threadIdx.x & 31;
    int half = lane >> 4;        // 0 or 1
    int ln = lane & 15;          // channel group: channels ln*8 .. ln*8+7
    float oe = 1.0f + __ldg(eps + layer);

    int beg = g_off[node];
    int end = g_off[node + 1];
    int deg = end - beg;

    const __half* hb = g_hh;
    float acc[8];
#pragma unroll
    for (int j = 0; j < 8; j++) acc[j] = 0.f;

    // self term (half 0 only, scaled by oe after neighbor sum would change
    // order; add scaled now: acc starts at oe*h)
    if (half == 0) {
        uint4 u = *(const uint4*)(hb + (size_t)node * D + ln * 8);
        __half2 h0 = *reinterpret_cast<__half2*>(&u.x);
        __half2 h1 = *reinterpret_cast<__half2*>(&u.y);
        __half2 h2 = *reinterpret_cast<__half2*>(&u.z);
        __half2 h3 = *reinterpret_cast<__half2*>(&u.w);
        float2 f0 = __half22float2(h0), f1 = __half22float2(h1);
        float2 f2 = __half22float2(h2), f3 = __half22float2(h3);
        acc[0] = oe * f0.x; acc[1] = oe * f0.y;
        acc[2] = oe * f1.x; acc[3] = oe * f1.y;
        acc[4] = oe * f2.x; acc[5] = oe * f2.y;
        acc[6] = oe * f3.x; acc[7] = oe * f3.y;
    }

    int i = beg;
    // 4 pairs (8 neighbors) per iteration; each half-warp does 4 of them
    for (; i + 7 < end; i += 8) {
        uint4 u[4];
#pragma unroll
        for (int j = 0; j < 4; j++) {
            int s = __ldg(g_csrc + i + j * 2 + half);
            u[j] = *(const uint4*)(hb + (size_t)s * D + ln * 8);
        }
#pragma unroll
        for (int j = 0; j < 4; j++) acc8(acc, u[j]);
    }
    // 1 pair per iteration
    for (; i + 1 < end; i += 2) {
        int s = __ldg(g_csrc + i + half);
        uint4 u = *(const uint4*)(hb + (size_t)s * D + ln * 8);
        acc8(acc, u);
    }
    // odd tail: half 0 only
    if (i < end && half == 0) {
        int s = __ldg(g_csrc + i);
        uint4 u = *(const uint4*)(hb + (size_t)s * D + ln * 8);
        acc8(acc, u);
    }
    (void)deg;

    // combine the two halves
#pragma unroll
    for (int j = 0; j < 8; j++)
        acc[j] += __shfl_xor_sync(0xffffffffu, acc[j], 16);

    if (half == 0) {
        float4 o0 = make_float4(acc[0], acc[1], acc[2], acc[3]);
        float4 o1 = make_float4(acc[4], acc[5], acc[6], acc[7]);
        *(float4*)(g_xin + (size_t)node * D + ln * 8) = o0;
        *(float4*)(g_xin + (size_t)node * D + ln * 8 + 4) = o1;
    }
}

// =====================================================================
// Split-bf16 tensor-core GEMM core.
// =====================================================================

struct SmemGemm {
    unsigned A[2][2][64 * 8];    // [buf][hi/lo][m*8 + kpair]
    unsigned B[2][2][128 * 8];   // [buf][hi/lo][n*8 + kpair]
};

// ---------------- GEMM1: x = xin @ W1 + b1, + BN stats ----------------
__global__ void __launch_bounds__(256) gemm1_tc_kernel(const float* __restrict__ b1,
                                                       int layer) {
    __shared__ SmemGemm sm;
    __shared__ float SredS[128], SredQ[128];

    int tid = threadIdx.x;
    int lane = tid & 31;
    int wid = tid >> 5;
    int wm = wid & 3;
    int wn = wid >> 2;
    int m0 = blockIdx.x * 64;

    if (tid < 128) { SredS[tid] = 0.f; SredQ[tid] = 0.f; }

    int lm = tid >> 2;
    int lq = (tid & 3);
    int gm_ld = m0 + lm;
    const unsigned* Wc = &g_w1p[layer][0][0][0][0];

    // prologue: chunk 0
    {
        float4 v = make_float4(0.f, 0.f, 0.f, 0.f);
        if (gm_ld < NN) v = *(const float4*)(g_xin + (size_t)gm_ld * D + lq * 4);
        unsigned hi[2], lo[2];
        split4(v, hi, lo);
        sm.A[0][0][lm * 8 + lq * 2] = hi[0];
        sm.A[0][0][lm * 8 + lq * 2 + 1] = hi[1];
        sm.A[0][1][lm * 8 + lq * 2] = lo[0];
        sm.A[0][1][lm * 8 + lq * 2 + 1] = lo[1];
        const uint4* Wg = (const uint4*)Wc;
        uint4 wh = Wg[tid], wl = Wg[tid + 256];
        ((uint4*)sm.B[0][0])[tid] = wh;
        ((uint4*)sm.B[0][1])[tid] = wl;
    }
    __syncthreads();

    float d[8][4];
#pragma unroll
    for (int nt = 0; nt < 8; nt++)
#pragma unroll
        for (int c = 0; c < 4; c++) d[nt][c] = 0.f;

    int kq = lane & 3;
    int gr = lane >> 2;
    int ca = wm * 16 + gr;

#pragma unroll
    for (int kk = 0; kk < 8; kk++) {
        const int cur = kk & 1;
        unsigned nah[2], nal[2];
        uint4 nwh, nwl;
        if (kk < 7) {
            float4 v = make_float4(0.f, 0.f, 0.f, 0.f);
            if (gm_ld < NN)
                v = *(const float4*)(g_xin + (size_t)gm_ld * D + (kk + 1) * 16 + lq * 4);
            split4(v, nah, nal);
            const uint4* Wg = (const uint4*)(Wc + (kk + 1) * 2048);
            nwh = Wg[tid]; nwl = Wg[tid + 256];
        }
        unsigned ah[4], al[4];
        ah[0] = sm.A[cur][0][ca * 8 + kq];
        ah[1] = sm.A[cur][0][(ca + 8) * 8 + kq];
        ah[2] = sm.A[cur][0][ca * 8 + kq + 4];
        ah[3] = sm.A[cur][0][(ca + 8) * 8 + kq + 4];
        al[0] = sm.A[cur][1][ca * 8 + kq];
        al[1] = sm.A[cur][1][(ca + 8) * 8 + kq];
        al[2] = sm.A[cur][1][ca * 8 + kq + 4];
        al[3] = sm.A[cur][1][(ca + 8) * 8 + kq + 4];
#pragma unroll
        for (int nt = 0; nt < 8; nt++) {
            int cb = wn * 64 + nt * 8 + gr;
            unsigned bh0 = sm.B[cur][0][cb * 8 + kq];
            unsigned bh1 = sm.B[cur][0][cb * 8 + kq + 4];
            unsigned bl0 = sm.B[cur][1][cb * 8 + kq];
            unsigned bl1 = sm.B[cur][1][cb * 8 + kq + 4];
            mma_bf16(d[nt], ah, bh0, bh1);
            mma_bf16(d[nt], ah, bl0, bl1);
            mma_bf16(d[nt], al, bh0, bh1);
        }
        if (kk < 7) {
            const int nxt = cur ^ 1;
            sm.A[nxt][0][lm * 8 + lq * 2] = nah[0];
            sm.A[nxt][0][lm * 8 + lq * 2 + 1] = nah[1];
            sm.A[nxt][1][lm * 8 + lq * 2] = nal[0];
            sm.A[nxt][1][lm * 8 + lq * 2 + 1] = nal[1];
            ((uint4*)sm.B[nxt][0])[tid] = nwh;
            ((uint4*)sm.B[nxt][1])[tid] = nwl;
            __syncthreads();
        }
    }

    // epilogue: bias, store x, BN stats
    int r0 = m0 + wm * 16 + gr;
    int r1 = r0 + 8;
    bool v0r = (r0 < NN), v1r = (r1 < NN);
#pragma unroll
    for (int nt = 0; nt < 8; nt++) {
        int c0 = wn * 64 + nt * 8 + 2 * kq;
        float bb0 = __ldg(b1 + (size_t)layer * D + c0);
        float bb1 = __ldg(b1 + (size_t)layer * D + c0 + 1);
        float x0 = d[nt][0] + bb0, x1 = d[nt][1] + bb1;
        float x2 = d[nt][2] + bb0, x3 = d[nt][3] + bb1;
        if (v0r) *(float2*)(g_x + (size_t)r0 * D + c0) = make_float2(x0, x1);
        if (v1r) *(float2*)(g_x + (size_t)r1 * D + c0) = make_float2(x2, x3);
        float sc0 = (v0r ? x0 : 0.f) + (v1r ? x2 : 0.f);
        float sc1 = (v0r ? x1 : 0.f) + (v1r ? x3 : 0.f);
        float qc0 = (v0r ? x0 * x0 : 0.f) + (v1r ? x2 * x2 : 0.f);
        float qc1 = (v0r ? x1 * x1 : 0.f) + (v1r ? x3 * x3 : 0.f);
#pragma unroll
        for (int o = 4; o <= 16; o <<= 1) {
            sc0 += __shfl_xor_sync(0xffffffffu, sc0, o);
            sc1 += __shfl_xor_sync(0xffffffffu, sc1, o);
            qc0 += __shfl_xor_sync(0xffffffffu, qc0, o);
            qc1 += __shfl_xor_sync(0xffffffffu, qc1, o);
        }
        if (gr == 0) {
            atomicAdd(&SredS[c0], sc0);
            atomicAdd(&SredS[c0 + 1], sc1);
            atomicAdd(&SredQ[c0], qc0);
            atomicAdd(&SredQ[c0 + 1], qc1);
        }
    }
    __syncthreads();
    if (tid < 128) {
        atomicAdd(&g_stats[layer][tid], SredS[tid]);
        atomicAdd(&g_stats[layer][D + tid], SredQ[tid]);
    }
}

// ---------------- GEMM2: h = relu( relu(BN(x)) @ W2 + b2 ) -> fp16 g_hh ----------------
__global__ void __launch_bounds__(256) gemm2_tc_kernel(const float* __restrict__ b2,
                                                       const float* __restrict__ gamma,
                                                       const float* __restrict__ beta,
                                                       int layer) {
    __shared__ SmemGemm sm;
    __shared__ float s_sc[128], s_sh[128];

    int tid = threadIdx.x;
    int lane = tid & 31;
    int wid = tid >> 5;
    int wm = wid & 3;
    int wn = wid >> 2;
    int m0 = blockIdx.x * 64;

    if (tid < 128) {
        float inv = 1.0f / (float)NN;
        float mu = g_stats[layer][tid] * inv;
        float var = g_stats[layer][D + tid] * inv - mu * mu;
        float rs = rsqrtf(var + 1e-5f);
        float sc = rs * __ldg(gamma + (size_t)layer * D + tid);
        s_sc[tid] = sc;
        s_sh[tid] = __ldg(beta + (size_t)layer * D + tid) - mu * sc;
    }
    __syncthreads();

    int lm = tid >> 2;
    int lq = (tid & 3);
    int gm_ld = m0 + lm;
    const unsigned* Wc = &g_w2p[layer][0][0][0][0];

    {
        float4 v = make_float4(0.f, 0.f, 0.f, 0.f);
        if (gm_ld < NN) {
            float4 xv = *(const float4*)(g_x + (size_t)gm_ld * D + lq * 4);
            int c = lq * 4;
            v.x = fmaxf(fmaf(xv.x, s_sc[c + 0], s_sh[c + 0]), 0.f);
            v.y = fmaxf(fmaf(xv.y, s_sc[c + 1], s_sh[c + 1]), 0.f);
            v.z = fmaxf(fmaf(xv.z, s_sc[c + 2], s_sh[c + 2]), 0.f);
            v.w = fmaxf(fmaf(xv.w, s_sc[c + 3], s_sh[c + 3]), 0.f);
        }
        unsigned hi[2], lo[2];
        split4(v, hi, lo);
        sm.A[0][0][lm * 8 + lq * 2] = hi[0];
        sm.A[0][0][lm * 8 + lq * 2 + 1] = hi[1];
        sm.A[0][1][lm * 8 + lq * 2] = lo[0];
        sm.A[0][1][lm * 8 + lq * 2 + 1] = lo[1];
        const uint4* Wg = (const uint4*)Wc;
        uint4 wh = Wg[tid], wl = Wg[tid + 256];
        ((uint4*)sm.B[0][0])[tid] = wh;
        ((uint4*)sm.B[0][1])[tid] = wl;
    }
    __syncthreads();

    float d[8][4];
#pragma unroll
    for (int nt = 0; nt < 8; nt++)
#pragma unroll
        for (int c = 0; c < 4; c++) d[nt][c] = 0.f;

    int kq = lane & 3;
    int gr = lane >> 2;
    int ca = wm * 16 + gr;

#pragma unroll
    for (int kk = 0; kk < 8; kk++) {
        const int cur = kk & 1;
        unsigned nah[2], nal[2];
        uint4 nwh, nwl;
        if (kk < 7) {
            float4 v = make_float4(0.f, 0.f, 0.f, 0.f);
            int kc = (kk + 1) * 16;
            if (gm_ld < NN) {
                float4 xv = *(const float4*)(g_x + (size_t)gm_ld * D + kc + lq * 4);
                int c = kc + lq * 4;
                v.x = fmaxf(fmaf(xv.x, s_sc[c + 0], s_sh[c + 0]), 0.f);
                v.y = fmaxf(fmaf(xv.y, s_sc[c + 1], s_sh[c + 1]), 0.f);
                v.z = fmaxf(fmaf(xv.z, s_sc[c + 2], s_sh[c + 2]), 0.f);
                v.w = fmaxf(fmaf(xv.w, s_sc[c + 3], s_sh[c + 3]), 0.f);
            }
            split4(v, nah, nal);
            const uint4* Wg = (const uint4*)(Wc + (kk + 1) * 2048);
            nwh = Wg[tid]; nwl = Wg[tid + 256];
        }
        unsigned ah[4], al[4];
        ah[0] = sm.A[cur][0][ca * 8 + kq];
        ah[1] = sm.A[cur][0][(ca + 8) * 8 + kq];
        ah[2] = sm.A[cur][0][ca * 8 + kq + 4];
        ah[3] = sm.A[cur][0][(ca + 8) * 8 + kq + 4];
        al[0] = sm.A[cur][1][ca * 8 + kq];
        al[1] = sm.A[cur][1][(ca + 8) * 8 + kq];
        al[2] = sm.A[cur][1][ca * 8 + kq + 4];
        al[3] = sm.A[cur][1][(ca + 8) * 8 + kq + 4];
#pragma unroll
        for (int nt = 0; nt < 8; nt++) {
            int cb = wn * 64 + nt * 8 + gr;
            unsigned bh0 = sm.B[cur][0][cb * 8 + kq];
            unsigned bh1 = sm.B[cur][0][cb * 8 + kq + 4];
            unsigned bl0 = sm.B[cur][1][cb * 8 + kq];
            unsigned bl1 = sm.B[cur][1][cb * 8 + kq + 4];
            mma_bf16(d[nt], ah, bh0, bh1);
            mma_bf16(d[nt], ah, bl0, bl1);
            mma_bf16(d[nt], al, bh0, bh1);
        }
        if (kk < 7) {
            const int nxt = cur ^ 1;
            sm.A[nxt][0][lm * 8 + lq * 2] = nah[0];
            sm.A[nxt][0][lm * 8 + lq * 2 + 1] = nah[1];
            sm.A[nxt][1][lm * 8 + lq * 2] = nal[0];
            sm.A[nxt][1][lm * 8 + lq * 2 + 1] = nal[1];
            ((uint4*)sm.B[nxt][0])[tid] = nwh;
            ((uint4*)sm.B[nxt][1])[tid] = nwl;
            __syncthreads();
        }
    }

    int r0 = m0 + wm * 16 + gr;
    int r1 = r0 + 8;
#pragma unroll
    for (int nt = 0; nt < 8; nt++) {
        int c0 = wn * 64 + nt * 8 + 2 * kq;
        float bb0 = __ldg(b2 + (size_t)layer * D + c0);
        float bb1 = __ldg(b2 + (size_t)layer * D + c0 + 1);
        if (r0 < NN) {
            *(__half2*)(g_hh + (size_t)r0 * D + c0) =
                __floats2half2_rn(fmaxf(d[nt][0] + bb0, 0.f),
                                  fmaxf(d[nt][1] + bb1, 0.f));
        }
        if (r1 < NN) {
            *(__half2*)(g_hh + (size_t)r1 * D + c0) =
                __floats2half2_rn(fmaxf(d[nt][2] + bb0, 0.f),
                                  fmaxf(d[nt][3] + bb1, 0.f));
        }
    }
}

// ---------------- GEMM3 (fp16 tensor core) ----------------
__global__ void __launch_bounds__(256) gemm3_tc_kernel(const float* __restrict__ bout,
                                                       float* __restrict__ out) {
    __shared__ unsigned sA[64 * 8];
    __shared__ unsigned sB[64 * 8];

    int tid = threadIdx.x;
    int lane = tid & 31;
    int wid = tid >> 5;
    int wm = wid & 3;
    int wn = wid >> 2;
    int m0 = blockIdx.x * 64;

    int lm = tid >> 2;
    int lq = tid & 3;
    int gm_ld = m0 + lm;

    float d[4][4];
#pragma unroll
    for (int nt = 0; nt < 4; nt++)
#pragma unroll
        for (int c = 0; c < 4; c++) d[nt][c] = 0.f;

    int kq = lane & 3;
    int gr = lane >> 2;
    int ca = wm * 16 + gr;

#pragma unroll
    for (int kk = 0; kk < 8; kk++) {
        uint2 a2 = make_uint2(0u, 0u);
        if (gm_ld < NN)
            a2 = *(const uint2*)(g_hh + (size_t)gm_ld * D + kk * 16 + lq * 4);
        sA[lm * 8 + lq * 2] = a2.x;
        sA[lm * 8 + lq * 2 + 1] = a2.y;
        if (tid < 128)
            ((uint4*)sB)[tid] = ((const uint4*)&g_w3p[kk][0][0])[tid];
        __syncthreads();

        unsigned a[4];
        a[0] = sA[ca * 8 + kq];
        a[1] = sA[(ca + 8) * 8 + kq];
        a[2] = sA[ca * 8 + kq + 4];
        a[3] = sA[(ca + 8) * 8 + kq + 4];
#pragma unroll
        for (int nt = 0; nt < 4; nt++) {
            int cb = wn * 32 + nt * 8 + gr;
            unsigned b0 = sB[cb * 8 + kq];
            unsigned b1 = sB[cb * 8 + kq + 4];
            mma_f16(d[nt], a, b0, b1);
        }
        __syncthreads();
    }

    int r0 = m0 + wm * 16 + gr;
    int r1 = r0 + 8;
#pragma unroll
    for (int nt = 0; nt < 4; nt++) {
        int c0 = wn * 32 + nt * 8 + 2 * kq;
        float bb0 = __ldg(bout + c0);
        float bb1 = __ldg(bout + c0 + 1);
        if (r0 < NN)
            *(float2*)(out + (size_t)r0 * OD + c0) =
                make_float2(d[nt][0] + bb0, d[nt][1] + bb1);
        if (r1 < NN)
            *(float2*)(out + (size_t)r1 * OD + c0) =
                make_float2(d[nt][2] + bb0, d[nt][3] + bb1);
    }
}

// ---------------- launch ----------------
extern "C" void kernel_launch(void* const* d_in, const int* in_sizes, int n_in,
                              void* d_out, int out_size) {
    const float* node_feat = (const float*)d_in[0];
    const int*   src       = (const int*)d_in[1];
    const int*   dst       = (const int*)d_in[2];
    const float* W1        = (const float*)d_in[3];
    const float* b1        = (const float*)d_in[4];
    const float* gamma     = (const float*)d_in[5];
    const float* beta      = (const float*)d_in[6];
    const float* W2        = (const float*)d_in[7];
    const float* b2        = (const float*)d_in[8];
    const float* eps       = (const float*)d_in[9];
    const float* Wout      = (const float*)d_in[10];
    const float* bout      = (const float*)d_in[11];
    float* out = (float*)d_out;

    const int gemm_grid  = (NN + 63) / 64;          // 782
    const int edge4_grid = (NE / 4 + 255) / 256;    // 1563
    const int gath_grid  = (NN + 7) / 8;            // 6250
    const int init_grid  = (R_TOT + 255) / 256;

    init_kernel<<<init_grid, 256>>>(node_feat, W1, W2, Wout, dst);
    scan1_kernel<<<NBLK, 256>>>();
    scan2_kernel<<<1, 256>>>();
    scan3_kernel<<<NBLK, 256>>>();
    csr_fill_kernel<<<edge4_grid, 256>>>(src, dst);

    for (int l = 0; l < NL; l++) {
        gather_kernel<<<gath_grid, 256>>>(eps, l);
        gemm1_tc_kernel<<<gemm_grid, 256>>>(b1, l);
        gemm2_tc_kernel<<<gemm_grid, 256>>>(b2, gamma, beta, l);
    }
    gemm3_tc_kernel<<<gemm_grid, 256>>>(bout, out);
}

// round 16
// speedup vs baseline: 1.0080x; 1.0080x over previous
#include <cuda_runtime.h>
#include <cuda_bf16.h>
#include <cuda_fp16.h>

#define NN 50000
#define NE 1600000
#define D  128
#define OD 64
#define NL 3
#define NBLK 196   // ceil(NN/256)

// ---------------- device scratch ----------------
__device__ __half g_hh[NN * D];        // node features (fp16)
__device__ float g_x[NN * D];          // MLP hidden pre-BN (fp32)
__device__ float g_xin[NN * D];        // (1+eps)h + agg (fp32)
__device__ float g_stats[NL][2 * D];   // per-layer per-channel sum & sumsq

// Pre-split weights, smem image layout:
// [layer][chunk(8)][hi/lo(2)][n(128)][kpair(8)]  (each uint = 2 bf16, low = even k)
__device__ unsigned g_w1p[NL][8][2][128][8];
__device__ unsigned g_w2p[NL][8][2][128][8];
// Wout in fp16, smem image: [chunk(8)][n(64)][kpair(8)]
__device__ unsigned g_w3p[8][64][8];

// CSR (dual-bucket counters/cursors).
// INVARIANT: g_cnt == 0 at kernel_launch entry (static zero-init on first
// call; csr_fill re-zeroes for subsequent calls).
__device__ int g_cnt[2][NN];
__device__ int g_cur[2][NN];
__device__ int g_off[NN + 1];
__device__ int g_csrc[NE];
__device__ int g_bsum[NBLK];

__device__ __forceinline__ unsigned pack_bf2(float a, float b) {
    __nv_bfloat162 t = __floats2bfloat162_rn(a, b);
    return *reinterpret_cast<unsigned*>(&t);
}
__device__ __forceinline__ unsigned pack_h2(float a, float b) {
    __half2 t = __floats2half2_rn(a, b);
    return *reinterpret_cast<unsigned*>(&t);
}
__device__ __forceinline__ float bf_hi(float x) {
    return __bfloat162float(__float2bfloat16_rn(x));
}
__device__ __forceinline__ float4 h4_to_f4(uint2 u) {
    __half2 a = *reinterpret_cast<__half2*>(&u.x);
    __half2 b = *reinterpret_cast<__half2*>(&u.y);
    float2 fa = __half22float2(a), fb = __half22float2(b);
    return make_float4(fa.x, fa.y, fb.x, fb.y);
}

__device__ __forceinline__ void mma_bf16(float* d, const unsigned* a,
                                         unsigned b0, unsigned b1) {
    asm volatile(
        "mma.sync.aligned.m16n8k16.row.col.f32.bf16.bf16.f32 "
        "{%0,%1,%2,%3}, {%4,%5,%6,%7}, {%8,%9}, {%0,%1,%2,%3};"
        : "+f"(d[0]), "+f"(d[1]), "+f"(d[2]), "+f"(d[3])
        : "r"(a[0]), "r"(a[1]), "r"(a[2]), "r"(a[3]), "r"(b0), "r"(b1));
}
__device__ __forceinline__ void mma_f16(float* d, const unsigned* a,
                                        unsigned b0, unsigned b1) {
    asm volatile(
        "mma.sync.aligned.m16n8k16.row.col.f32.f16.f16.f32 "
        "{%0,%1,%2,%3}, {%4,%5,%6,%7}, {%8,%9}, {%0,%1,%2,%3};"
        : "+f"(d[0]), "+f"(d[1]), "+f"(d[2]), "+f"(d[3])
        : "r"(a[0]), "r"(a[1]), "r"(a[2]), "r"(a[3]), "r"(b0), "r"(b1));
}

__device__ __forceinline__ void split4(float4 v, unsigned* hi, unsigned* lo) {
    float h0 = bf_hi(v.x), h1 = bf_hi(v.y), h2 = bf_hi(v.z), h3 = bf_hi(v.w);
    hi[0] = pack_bf2(h0, h1);
    hi[1] = pack_bf2(h2, h3);
    lo[0] = pack_bf2(v.x - h0, v.y - h1);
    lo[1] = pack_bf2(v.z - h2, v.w - h3);
}

// ---------------- fused init + histogram ----------------
#define R_HI   (NE / 4)              // 400,000
#define R_NF   (NN * D / 4)          // 1,600,000
#define R_W    (NL * 64 * 128)       // 24,576
#define R_W3   (64 * 64)             // 4,096
#define R_ST   (NL * 2 * D)          // 768
#define R_TOT  (R_HI + R_NF + R_W + R_W3 + R_ST + 1)

__global__ void init_kernel(const float* __restrict__ nf,
                            const float* __restrict__ W1,
                            const float* __restrict__ W2,
                            const float* __restrict__ Wout,
                            const int* __restrict__ dst) {
    int i = blockIdx.x * blockDim.x + threadIdx.x;
    if (i < R_HI) {
        int b = (i < NE / 8) ? 0 : 1;
        int4 d = __ldg((const int4*)dst + i);
        atomicAdd(&g_cnt[b][d.x], 1);
        atomicAdd(&g_cnt[b][d.y], 1);
        atomicAdd(&g_cnt[b][d.z], 1);
        atomicAdd(&g_cnt[b][d.w], 1);
        return;
    }
    int r = i - R_HI;
    if (r < R_NF) {
        float4 v = __ldg((const float4*)nf + r);
        __half2* p = (__half2*)g_hh + r * 2;
        p[0] = __floats2half2_rn(v.x, v.y);
        p[1] = __floats2half2_rn(v.z, v.w);
        return;
    }
    r -= R_NF;
    if (r < R_W) {
        int n = r & 127;
        int kp = (r >> 7) & 63;
        int l = r >> 13;
        int k0 = kp * 2;
        int chunk = k0 >> 4;
        int kpi = (k0 & 15) >> 1;
        {
            float w0 = __ldg(W1 + (size_t)l * D * D + k0 * D + n);
            float w1 = __ldg(W1 + (size_t)l * D * D + (k0 + 1) * D + n);
            float h0 = bf_hi(w0), h1 = bf_hi(w1);
            g_w1p[l][chunk][0][n][kpi] = pack_bf2(h0, h1);
            g_w1p[l][chunk][1][n][kpi] = pack_bf2(w0 - h0, w1 - h1);
        }
        {
            float w0 = __ldg(W2 + (size_t)l * D * D + k0 * D + n);
            float w1 = __ldg(W2 + (size_t)l * D * D + (k0 + 1) * D + n);
            float h0 = bf_hi(w0), h1 = bf_hi(w1);
            g_w2p[l][chunk][0][n][kpi] = pack_bf2(h0, h1);
            g_w2p[l][chunk][1][n][kpi] = pack_bf2(w0 - h0, w1 - h1);
        }
        return;
    }
    r -= R_W;
    if (r < R_W3) {
        int n = r & 63;
        int kp = r >> 6;
        int k0 = kp * 2;
        int chunk = k0 >> 4;
        int kpi = (k0 & 15) >> 1;
        float w0 = __ldg(Wout + k0 * OD + n);
        float w1 = __ldg(Wout + (k0 + 1) * OD + n);
        g_w3p[chunk][n][kpi] = pack_h2(w0, w1);
        return;
    }
    r -= R_W3;
    if (r < R_ST) { ((float*)g_stats)[r] = 0.f; return; }
    r -= R_ST;
    if (r == 0) g_off[0] = 0;
}

// --- scan1: per-block inclusive scan, writes local prefixes + block totals ---
__global__ void scan1_kernel() {
    int b = blockIdx.x, tid = threadIdx.x;
    int i = b * 256 + tid;
    int c0 = (i < NN) ? g_cnt[0][i] : 0;
    int c1 = (i < NN) ? g_cnt[1][i] : 0;
    int v = c0 + c1;
    int lane = tid & 31, w = tid >> 5;
    int x = v;
#pragma unroll
    for (int o = 1; o < 32; o <<= 1) {
        int t = __shfl_up_sync(0xffffffffu, x, o);
        if (lane >= o) x += t;
    }
    __shared__ int wsum[8];
    if (lane == 31) wsum[w] = x;
    __syncthreads();
    if (w == 0 && lane < 8) {
        int y = wsum[lane];
#pragma unroll
        for (int o = 1; o < 8; o <<= 1) {
            int t = __shfl_up_sync(0xffu, y, o);
            if (lane >= o) y += t;
        }
        wsum[lane] = y;
    }
    __syncthreads();
    int incl = x + (w > 0 ? wsum[w - 1] : 0);
    if (i < NN) {
        g_off[i + 1] = incl;
        g_cur[0][i] = incl - v;
        g_cur[1][i] = incl - v + c0;
    }
    if (tid == 255) g_bsum[b] = incl;
}

// --- scan23 (merged): each block computes its own base = sum_{j<b} bsum[j]
// (196 ints, one warp pass — cheap even replicated 196x), then applies it. ---
__global__ void scan23_kernel() {
    __shared__ int sbase;
    int b = blockIdx.x, tid = threadIdx.x;
    if (tid < 32) {
        // lane t sums bsum[t], bsum[t+32], ... over j < b
        int lane = tid;
        int part = 0;
        for (int j = lane; j < b; j += 32) part += g_bsum[j];
#pragma unroll
        for (int o = 16; o > 0; o >>= 1)
            part += __shfl_xor_sync(0xffffffffu, part, o);
        if (lane == 0) sbase = part;
    }
    __syncthreads();
    int base = sbase;
    int i = b * 256 + tid;
    if (i < NN) {
        g_off[i + 1] += base;
        g_cur[0][i] += base;
        g_cur[1][i] += base;
    }
}

// fill + re-zero g_cnt for the NEXT call
__global__ void csr_fill_kernel(const int* __restrict__ src,
                                const int* __restrict__ dst) {
    int i = blockIdx.x * blockDim.x + threadIdx.x;
    if (i < NN) { g_cnt[0][i] = 0; g_cnt[1][i] = 0; }
    if (i >= NE / 4) return;
    int b = (i < NE / 8) ? 0 : 1;
    int4 s = __ldg((const int4*)src + i);
    int4 d = __ldg((const int4*)dst + i);
    int p0 = atomicAdd(&g_cur[b][d.x], 1);
    int p1 = atomicAdd(&g_cur[b][d.y], 1);
    int p2 = atomicAdd(&g_cur[b][d.z], 1);
    int p3 = atomicAdd(&g_cur[b][d.w], 1);
    g_csrc[p0] = s.x;
    g_csrc[p1] = s.y;
    g_csrc[p2] = s.z;
    g_csrc[p3] = s.w;
}

// ---------------- gather (fp16 h, R14 uint2 8-deep — proven best) ----------------
__global__ void __launch_bounds__(256) gather_kernel(const float* __restrict__ eps,
                                                     int layer) {
    int node = blockIdx.x * 8 + (threadIdx.x >> 5);
    if (node >= NN) return;
    int lane = threadIdx.x & 31;
    float oe = 1.0f + __ldg(eps + layer);

    int beg = g_off[node];
    int end = g_off[node + 1];

    const __half* hb = g_hh;
    float4 hv = h4_to_f4(*(const uint2*)(hb + (size_t)node * D + lane * 4));
    float4 acc;
    acc.x = oe * hv.x; acc.y = oe * hv.y; acc.z = oe * hv.z; acc.w = oe * hv.w;

    int i = beg;
    for (; i + 7 < end; i += 8) {
        uint2 u[8];
#pragma unroll
        for (int j = 0; j < 8; j++) {
            int s = __ldg(g_csrc + i + j);
            u[j] = *(const uint2*)(hb + (size_t)s * D + lane * 4);
        }
#pragma unroll
        for (int j = 0; j < 8; j++) {
            float4 v = h4_to_f4(u[j]);
            acc.x += v.x; acc.y += v.y; acc.z += v.z; acc.w += v.w;
        }
    }
    for (; i + 3 < end; i += 4) {
        uint2 u[4];
#pragma unroll
        for (int j = 0; j < 4; j++) {
            int s = __ldg(g_csrc + i + j);
            u[j] = *(const uint2*)(hb + (size_t)s * D + lane * 4);
        }
#pragma unroll
        for (int j = 0; j < 4; j++) {
            float4 v = h4_to_f4(u[j]);
            acc.x += v.x; acc.y += v.y; acc.z += v.z; acc.w += v.w;
        }
    }
    for (; i < end; i++) {
        int s = __ldg(g_csrc + i);
        float4 v = h4_to_f4(*(const uint2*)(hb + (size_t)s * D + lane * 4));
        acc.x += v.x; acc.y += v.y; acc.z += v.z; acc.w += v.w;
    }
    *(float4*)(g_xin + (size_t)node * D + lane * 4) = acc;
}

// =====================================================================
// Split-bf16 tensor-core GEMM core.
// =====================================================================

struct SmemGemm {
    unsigned A[2][2][64 * 8];    // [buf][hi/lo][m*8 + kpair]
    unsigned B[2][2][128 * 8];   // [buf][hi/lo][n*8 + kpair]
};

// ---------------- GEMM1: x = xin @ W1 + b1, + BN stats ----------------
__global__ void __launch_bounds__(256) gemm1_tc_kernel(const float* __restrict__ b1,
                                                       int layer) {
    __shared__ SmemGemm sm;
    __shared__ float SredS[128], SredQ[128];

    int tid = threadIdx.x;
    int lane = tid & 31;
    int wid = tid >> 5;
    int wm = wid & 3;
    int wn = wid >> 2;
    int m0 = blockIdx.x * 64;

    if (tid < 128) { SredS[tid] = 0.f; SredQ[tid] = 0.f; }

    int lm = tid >> 2;
    int lq = (tid & 3);
    int gm_ld = m0 + lm;
    const unsigned* Wc = &g_w1p[layer][0][0][0][0];

    // prologue: chunk 0
    {
        float4 v = make_float4(0.f, 0.f, 0.f, 0.f);
        if (gm_ld < NN) v = *(const float4*)(g_xin + (size_t)gm_ld * D + lq * 4);
        unsigned hi[2], lo[2];
        split4(v, hi, lo);
        sm.A[0][0][lm * 8 + lq * 2] = hi[0];
        sm.A[0][0][lm * 8 + lq * 2 + 1] = hi[1];
        sm.A[0][1][lm * 8 + lq * 2] = lo[0];
        sm.A[0][1][lm * 8 + lq * 2 + 1] = lo[1];
        const uint4* Wg = (const uint4*)Wc;
        uint4 wh = Wg[tid], wl = Wg[tid + 256];
        ((uint4*)sm.B[0][0])[tid] = wh;
        ((uint4*)sm.B[0][1])[tid] = wl;
    }
    __syncthreads();

    float d[8][4];
#pragma unroll
    for (int nt = 0; nt < 8; nt++)
#pragma unroll
        for (int c = 0; c < 4; c++) d[nt][c] = 0.f;

    int kq = lane & 3;
    int gr = lane >> 2;
    int ca = wm * 16 + gr;

#pragma unroll
    for (int kk = 0; kk < 8; kk++) {
        const int cur = kk & 1;
        unsigned nah[2], nal[2];
        uint4 nwh, nwl;
        if (kk < 7) {
            float4 v = make_float4(0.f, 0.f, 0.f, 0.f);
            if (gm_ld < NN)
                v = *(const float4*)(g_xin + (size_t)gm_ld * D + (kk + 1) * 16 + lq * 4);
            split4(v, nah, nal);
            const uint4* Wg = (const uint4*)(Wc + (kk + 1) * 2048);
            nwh = Wg[tid]; nwl = Wg[tid + 256];
        }
        unsigned ah[4], al[4];
        ah[0] = sm.A[cur][0][ca * 8 + kq];
        ah[1] = sm.A[cur][0][(ca + 8) * 8 + kq];
        ah[2] = sm.A[cur][0][ca * 8 + kq + 4];
        ah[3] = sm.A[cur][0][(ca + 8) * 8 + kq + 4];
        al[0] = sm.A[cur][1][ca * 8 + kq];
        al[1] = sm.A[cur][1][(ca + 8) * 8 + kq];
        al[2] = sm.A[cur][1][ca * 8 + kq + 4];
        al[3] = sm.A[cur][1][(ca + 8) * 8 + kq + 4];
#pragma unroll
        for (int nt = 0; nt < 8; nt++) {
            int cb = wn * 64 + nt * 8 + gr;
            unsigned bh0 = sm.B[cur][0][cb * 8 + kq];
            unsigned bh1 = sm.B[cur][0][cb * 8 + kq + 4];
            unsigned bl0 = sm.B[cur][1][cb * 8 + kq];
            unsigned bl1 = sm.B[cur][1][cb * 8 + kq + 4];
            mma_bf16(d[nt], ah, bh0, bh1);
            mma_bf16(d[nt], ah, bl0, bl1);
            mma_bf16(d[nt], al, bh0, bh1);
        }
        if (kk < 7) {
            const int nxt = cur ^ 1;
            sm.A[nxt][0][lm * 8 + lq * 2] = nah[0];
            sm.A[nxt][0][lm * 8 + lq * 2 + 1] = nah[1];
            sm.A[nxt][1][lm * 8 + lq * 2] = nal[0];
            sm.A[nxt][1][lm * 8 + lq * 2 + 1] = nal[1];
            ((uint4*)sm.B[nxt][0])[tid] = nwh;
            ((uint4*)sm.B[nxt][1])[tid] = nwl;
            __syncthreads();
        }
    }

    // epilogue: bias, store x, BN stats
    int r0 = m0 + wm * 16 + gr;
    int r1 = r0 + 8;
    bool v0r = (r0 < NN), v1r = (r1 < NN);
#pragma unroll
    for (int nt = 0; nt < 8; nt++) {
        int c0 = wn * 64 + nt * 8 + 2 * kq;
        float bb0 = __ldg(b1 + (size_t)layer * D + c0);
        float bb1 = __ldg(b1 + (size_t)layer * D + c0 + 1);
        float x0 = d[nt][0] + bb0, x1 = d[nt][1] + bb1;
        float x2 = d[nt][2] + bb0, x3 = d[nt][3] + bb1;
        if (v0r) *(float2*)(g_x + (size_t)r0 * D + c0) = make_float2(x0, x1);
        if (v1r) *(float2*)(g_x + (size_t)r1 * D + c0) = make_float2(x2, x3);
        float sc0 = (v0r ? x0 : 0.f) + (v1r ? x2 : 0.f);
        float sc1 = (v0r ? x1 : 0.f) + (v1r ? x3 : 0.f);
        float qc0 = (v0r ? x0 * x0 : 0.f) + (v1r ? x2 * x2 : 0.f);
        float qc1 = (v0r ? x1 * x1 : 0.f) + (v1r ? x3 * x3 : 0.f);
#pragma unroll
        for (int o = 4; o <= 16; o <<= 1) {
            sc0 += __shfl_xor_sync(0xffffffffu, sc0, o);
            sc1 += __shfl_xor_sync(0xffffffffu, sc1, o);
            qc0 += __shfl_xor_sync(0xffffffffu, qc0, o);
            qc1 += __shfl_xor_sync(0xffffffffu, qc1, o);
        }
        if (gr == 0) {
            atomicAdd(&SredS[c0], sc0);
            atomicAdd(&SredS[c0 + 1], sc1);
            atomicAdd(&SredQ[c0], qc0);
            atomicAdd(&SredQ[c0 + 1], qc1);
        }
    }
    __syncthreads();
    if (tid < 128) {
        atomicAdd(&g_stats[layer][tid], SredS[tid]);
        atomicAdd(&g_stats[layer][D + tid], SredQ[tid]);
    }
}

// ---------------- GEMM2: h = relu( relu(BN(x)) @ W2 + b2 ) -> fp16 g_hh ----------------
__global__ void __launch_bounds__(256) gemm2_tc_kernel(const float* __restrict__ b2,
                                                       const float* __restrict__ gamma,
                                                       const float* __restrict__ beta,
                                                       int layer) {
    __shared__ SmemGemm sm;
    __shared__ float s_sc[128], s_sh[128];

    int tid = threadIdx.x;
    int lane = tid & 31;
    int wid = tid >> 5;
    int wm = wid & 3;
    int wn = wid >> 2;
    int m0 = blockIdx.x * 64;

    if (tid < 128) {
        float inv = 1.0f / (float)NN;
        float mu = g_stats[layer][tid] * inv;
        float var = g_stats[layer][D + tid] * inv - mu * mu;
        float rs = rsqrtf(var + 1e-5f);
        float sc = rs * __ldg(gamma + (size_t)layer * D + tid);
        s_sc[tid] = sc;
        s_sh[tid] = __ldg(beta + (size_t)layer * D + tid) - mu * sc;
    }
    __syncthreads();

    int lm = tid >> 2;
    int lq = (tid & 3);
    int gm_ld = m0 + lm;
    const unsigned* Wc = &g_w2p[layer][0][0][0][0];

    {
        float4 v = make_float4(0.f, 0.f, 0.f, 0.f);
        if (gm_ld < NN) {
            float4 xv = *(const float4*)(g_x + (size_t)gm_ld * D + lq * 4);
            int c = lq * 4;
            v.x = fmaxf(fmaf(xv.x, s_sc[c + 0], s_sh[c + 0]), 0.f);
            v.y = fmaxf(fmaf(xv.y, s_sc[c + 1], s_sh[c + 1]), 0.f);
            v.z = fmaxf(fmaf(xv.z, s_sc[c + 2], s_sh[c + 2]), 0.f);
            v.w = fmaxf(fmaf(xv.w, s_sc[c + 3], s_sh[c + 3]), 0.f);
        }
        unsigned hi[2], lo[2];
        split4(v, hi, lo);
        sm.A[0][0][lm * 8 + lq * 2] = hi[0];
        sm.A[0][0][lm * 8 + lq * 2 + 1] = hi[1];
        sm.A[0][1][lm * 8 + lq * 2] = lo[0];
        sm.A[0][1][lm * 8 + lq * 2 + 1] = lo[1];
        const uint4* Wg = (const uint4*)Wc;
        uint4 wh = Wg[tid], wl = Wg[tid + 256];
        ((uint4*)sm.B[0][0])[tid] = wh;
        ((uint4*)sm.B[0][1])[tid] = wl;
    }
    __syncthreads();

    float d[8][4];
#pragma unroll
    for (int nt = 0; nt < 8; nt++)
#pragma unroll
        for (int c = 0; c < 4; c++) d[nt][c] = 0.f;

    int kq = lane & 3;
    int gr = lane >> 2;
    int ca = wm * 16 + gr;

#pragma unroll
    for (int kk = 0; kk < 8; kk++) {
        const int cur = kk & 1;
        unsigned nah[2], nal[2];
        uint4 nwh, nwl;
        if (kk < 7) {
            float4 v = make_float4(0.f, 0.f, 0.f, 0.f);
            int kc = (kk + 1) * 16;
            if (gm_ld < NN) {
                float4 xv = *(const float4*)(g_x + (size_t)gm_ld * D + kc + lq * 4);
                int c = kc + lq * 4;
                v.x = fmaxf(fmaf(xv.x, s_sc[c + 0], s_sh[c + 0]), 0.f);
                v.y = fmaxf(fmaf(xv.y, s_sc[c + 1], s_sh[c + 1]), 0.f);
                v.z = fmaxf(fmaf(xv.z, s_sc[c + 2], s_sh[c + 2]), 0.f);
                v.w = fmaxf(fmaf(xv.w, s_sc[c + 3], s_sh[c + 3]), 0.f);
            }
            split4(v, nah, nal);
            const uint4* Wg = (const uint4*)(Wc + (kk + 1) * 2048);
            nwh = Wg[tid]; nwl = Wg[tid + 256];
        }
        unsigned ah[4], al[4];
        ah[0] = sm.A[cur][0][ca * 8 + kq];
        ah[1] = sm.A[cur][0][(ca + 8) * 8 + kq];
        ah[2] = sm.A[cur][0][ca * 8 + kq + 4];
        ah[3] = sm.A[cur][0][(ca + 8) * 8 + kq + 4];
        al[0] = sm.A[cur][1][ca * 8 + kq];
        al[1] = sm.A[cur][1][(ca + 8) * 8 + kq];
        al[2] = sm.A[cur][1][ca * 8 + kq + 4];
        al[3] = sm.A[cur][1][(ca + 8) * 8 + kq + 4];
#pragma unroll
        for (int nt = 0; nt < 8; nt++) {
            int cb = wn * 64 + nt * 8 + gr;
            unsigned bh0 = sm.B[cur][0][cb * 8 + kq];
            unsigned bh1 = sm.B[cur][0][cb * 8 + kq + 4];
            unsigned bl0 = sm.B[cur][1][cb * 8 + kq];
            unsigned bl1 = sm.B[cur][1][cb * 8 + kq + 4];
            mma_bf16(d[nt], ah, bh0, bh1);
            mma_bf16(d[nt], ah, bl0, bl1);
            mma_bf16(d[nt], al, bh0, bh1);
        }
        if (kk < 7) {
            const int nxt = cur ^ 1;
            sm.A[nxt][0][lm * 8 + lq * 2] = nah[0];
            sm.A[nxt][0][lm * 8 + lq * 2 + 1] = nah[1];
            sm.A[nxt][1][lm * 8 + lq * 2] = nal[0];
            sm.A[nxt][1][lm * 8 + lq * 2 + 1] = nal[1];
            ((uint4*)sm.B[nxt][0])[tid] = nwh;
            ((uint4*)sm.B[nxt][1])[tid] = nwl;
            __syncthreads();
        }
    }

    int r0 = m0 + wm * 16 + gr;
    int r1 = r0 + 8;
#pragma unroll
    for (int nt = 0; nt < 8; nt++) {
        int c0 = wn * 64 + nt * 8 + 2 * kq;
        float bb0 = __ldg(b2 + (size_t)layer * D + c0);
        float bb1 = __ldg(b2 + (size_t)layer * D + c0 + 1);
        if (r0 < NN) {
            *(__half2*)(g_hh + (size_t)r0 * D + c0) =
                __floats2half2_rn(fmaxf(d[nt][0] + bb0, 0.f),
                                  fmaxf(d[nt][1] + bb1, 0.f));
        }
        if (r1 < NN) {
            *(__half2*)(g_hh + (size_t)r1 * D + c0) =
                __floats2half2_rn(fmaxf(d[nt][2] + bb0, 0.f),
                                  fmaxf(d[nt][3] + bb1, 0.f));
        }
    }
}

// ---------------- GEMM3 (fp16 tensor core) ----------------
__global__ void __launch_bounds__(256) gemm3_tc_kernel(const float* __restrict__ bout,
                                                       float* __restrict__ out) {
    __shared__ unsigned sA[64 * 8];
    __shared__ unsigned sB[64 * 8];

    int tid = threadIdx.x;
    int lane = tid & 31;
    int wid = tid >> 5;
    int wm = wid & 3;
    int wn = wid >> 2;
    int m0 = blockIdx.x * 64;

    int lm = tid >> 2;
    int lq = tid & 3;
    int gm_ld = m0 + lm;

    float d[4][4];
#pragma unroll
    for (int nt = 0; nt < 4; nt++)
#pragma unroll
        for (int c = 0; c < 4; c++) d[nt][c] = 0.f;

    int kq = lane & 3;
    int gr = lane >> 2;
    int ca = wm * 16 + gr;

#pragma unroll
    for (int kk = 0; kk < 8; kk++) {
        uint2 a2 = make_uint2(0u, 0u);
        if (gm_ld < NN)
            a2 = *(const uint2*)(g_hh + (size_t)gm_ld * D + kk * 16 + lq * 4);
        sA[lm * 8 + lq * 2] = a2.x;
        sA[lm * 8 + lq * 2 + 1] = a2.y;
        if (tid < 128)
            ((uint4*)sB)[tid] = ((const uint4*)&g_w3p[kk][0][0])[tid];
        __syncthreads();

        unsigned a[4];
        a[0] = sA[ca * 8 + kq];
        a[1] = sA[(ca + 8) * 8 + kq];
        a[2] = sA[ca * 8 + kq + 4];
        a[3] = sA[(ca + 8) * 8 + kq + 4];
#pragma unroll
        for (int nt = 0; nt < 4; nt++) {
            int cb = wn * 32 + nt * 8 + gr;
            unsigned b0 = sB[cb * 8 + kq];
            unsigned b1 = sB[cb * 8 + kq + 4];
            mma_f16(d[nt], a, b0, b1);
        }
        __syncthreads();
    }

    int r0 = m0 + wm * 16 + gr;
    int r1 = r0 + 8;
#pragma unroll
    for (int nt = 0; nt < 4; nt++) {
        int c0 = wn * 32 + nt * 8 + 2 * kq;
        float bb0 = __ldg(bout + c0);
        float bb1 = __ldg(bout + c0 + 1);
        if (r0 < NN)
            *(float2*)(out + (size_t)r0 * OD + c0) =
                make_float2(d[nt][0] + bb0, d[nt][1] + bb1);
        if (r1 < NN)
            *(float2*)(out + (size_t)r1 * OD + c0) =
                make_float2(d[nt][2] + bb0, d[nt][3] + bb1);
    }
}

// ---------------- launch ----------------
extern "C" void kernel_launch(void* const* d_in, const int* in_sizes, int n_in,
                              void* d_out, int out_size) {
    const float* node_feat = (const float*)d_in[0];
    const int*   src       = (const int*)d_in[1];
    const int*   dst       = (const int*)d_in[2];
    const float* W1        = (const float*)d_in[3];
    const float* b1        = (const float*)d_in[4];
    const float* gamma     = (const float*)d_in[5];
    const float* beta      = (const float*)d_in[6];
    const float* W2        = (const float*)d_in[7];
    const float* b2        = (const float*)d_in[8];
    const float* eps       = (const float*)d_in[9];
    const float* Wout      = (const float*)d_in[10];
    const float* bout      = (const float*)d_in[11];
    float* out = (float*)d_out;

    const int gemm_grid  = (NN + 63) / 64;          // 782
    const int edge4_grid = (NE / 4 + 255) / 256;    // 1563
    const int gath_grid  = (NN + 7) / 8;            // 6250
    const int init_grid  = (R_TOT + 255) / 256;

    init_kernel<<<init_grid, 256>>>(node_feat, W1, W2, Wout, dst);
    scan1_kernel<<<NBLK, 256>>>();
    scan23_kernel<<<NBLK, 256>>>();
    csr_fill_kernel<<<edge4_grid, 256>>>(src, dst);

    for (int l = 0; l < NL; l++) {
        gather_kernel<<<gath_grid, 256>>>(eps, l);
        gemm1_tc_kernel<<<gemm_grid, 256>>>(b1, l);
        gemm2_tc_kernel<<<gemm_grid, 256>>>(b2, gamma, beta, l);
    }
    gemm3_tc_kernel<<<gemm_grid, 256>>>(bout, out);
}

// round 17
// speedup vs baseline: 1.0381x; 1.0298x over previous
#include <cuda_runtime.h>
#include <cuda_bf16.h>
#include <cuda_fp16.h>

#define NN 50000
#define NE 1600000
#define D  128
#define OD 64
#define NL 3
#define NBLK 196   // ceil(NN/256)
#define NB  4      // CSR buckets
#define EQ  (NE / 4 / NB)   // 100000 int4-items per bucket

// ---------------- device scratch ----------------
__device__ __half g_hh[NN * D];        // node features (fp16)
__device__ float g_x[NN * D];          // MLP hidden pre-BN (fp32)
__device__ float g_xin[NN * D];        // (1+eps)h + agg (fp32)
__device__ float g_stats[NL][2 * D];   // per-layer per-channel sum & sumsq

// Pre-split weights (smem image layouts)
__device__ unsigned g_w1p[NL][8][2][128][8];
__device__ unsigned g_w2p[NL][8][2][128][8];
__device__ unsigned g_w3p[8][64][8];

// CSR (4-bucket counters/cursors).
// INVARIANT: g_cnt == 0 at kernel_launch entry (static zero-init first call;
// csr_fill re-zeroes for subsequent calls).
__device__ int g_cnt[NB][NN];
__device__ int g_cur[NB][NN];
__device__ int g_off[NN + 1];
__device__ int g_csrc[NE];
__device__ int g_bsum[NBLK];

__device__ __forceinline__ unsigned pack_bf2(float a, float b) {
    __nv_bfloat162 t = __floats2bfloat162_rn(a, b);
    return *reinterpret_cast<unsigned*>(&t);
}
__device__ __forceinline__ unsigned pack_h2(float a, float b) {
    __half2 t = __floats2half2_rn(a, b);
    return *reinterpret_cast<unsigned*>(&t);
}
__device__ __forceinline__ float bf_hi(float x) {
    return __bfloat162float(__float2bfloat16_rn(x));
}
__device__ __forceinline__ float4 h4_to_f4(uint2 u) {
    __half2 a = *reinterpret_cast<__half2*>(&u.x);
    __half2 b = *reinterpret_cast<__half2*>(&u.y);
    float2 fa = __half22float2(a), fb = __half22float2(b);
    return make_float4(fa.x, fa.y, fb.x, fb.y);
}

__device__ __forceinline__ void mma_bf16(float* d, const unsigned* a,
                                         unsigned b0, unsigned b1) {
    asm volatile(
        "mma.sync.aligned.m16n8k16.row.col.f32.bf16.bf16.f32 "
        "{%0,%1,%2,%3}, {%4,%5,%6,%7}, {%8,%9}, {%0,%1,%2,%3};"
        : "+f"(d[0]), "+f"(d[1]), "+f"(d[2]), "+f"(d[3])
        : "r"(a[0]), "r"(a[1]), "r"(a[2]), "r"(a[3]), "r"(b0), "r"(b1));
}
__device__ __forceinline__ void mma_f16(float* d, const unsigned* a,
                                        unsigned b0, unsigned b1) {
    asm volatile(
        "mma.sync.aligned.m16n8k16.row.col.f32.f16.f16.f32 "
        "{%0,%1,%2,%3}, {%4,%5,%6,%7}, {%8,%9}, {%0,%1,%2,%3};"
        : "+f"(d[0]), "+f"(d[1]), "+f"(d[2]), "+f"(d[3])
        : "r"(a[0]), "r"(a[1]), "r"(a[2]), "r"(a[3]), "r"(b0), "r"(b1));
}

__device__ __forceinline__ void split4(float4 v, unsigned* hi, unsigned* lo) {
    float h0 = bf_hi(v.x), h1 = bf_hi(v.y), h2 = bf_hi(v.z), h3 = bf_hi(v.w);
    hi[0] = pack_bf2(h0, h1);
    hi[1] = pack_bf2(h2, h3);
    lo[0] = pack_bf2(v.x - h0, v.y - h1);
    lo[1] = pack_bf2(v.z - h2, v.w - h3);
}

__device__ __forceinline__ int bucket_of(int i) {
    // i in [0, NE/4); quarter split
    return (i >= 2 * EQ) ? ((i >= 3 * EQ) ? 3 : 2) : ((i >= EQ) ? 1 : 0);
}

// ---------------- fused init + histogram ----------------
#define R_HI   (NE / 4)
#define R_NF   (NN * D / 4)
#define R_W    (NL * 64 * 128)
#define R_W3   (64 * 64)
#define R_ST   (NL * 2 * D)
#define R_TOT  (R_HI + R_NF + R_W + R_W3 + R_ST + 1)

__global__ void init_kernel(const float* __restrict__ nf,
                            const float* __restrict__ W1,
                            const float* __restrict__ W2,
                            const float* __restrict__ Wout,
                            const int* __restrict__ dst) {
    int i = blockIdx.x * blockDim.x + threadIdx.x;
    if (i < R_HI) {
        int b = bucket_of(i);
        int4 d = __ldg((const int4*)dst + i);
        atomicAdd(&g_cnt[b][d.x], 1);
        atomicAdd(&g_cnt[b][d.y], 1);
        atomicAdd(&g_cnt[b][d.z], 1);
        atomicAdd(&g_cnt[b][d.w], 1);
        return;
    }
    int r = i - R_HI;
    if (r < R_NF) {
        float4 v = __ldg((const float4*)nf + r);
        __half2* p = (__half2*)g_hh + r * 2;
        p[0] = __floats2half2_rn(v.x, v.y);
        p[1] = __floats2half2_rn(v.z, v.w);
        return;
    }
    r -= R_NF;
    if (r < R_W) {
        int n = r & 127;
        int kp = (r >> 7) & 63;
        int l = r >> 13;
        int k0 = kp * 2;
        int chunk = k0 >> 4;
        int kpi = (k0 & 15) >> 1;
        {
            float w0 = __ldg(W1 + (size_t)l * D * D + k0 * D + n);
            float w1 = __ldg(W1 + (size_t)l * D * D + (k0 + 1) * D + n);
            float h0 = bf_hi(w0), h1 = bf_hi(w1);
            g_w1p[l][chunk][0][n][kpi] = pack_bf2(h0, h1);
            g_w1p[l][chunk][1][n][kpi] = pack_bf2(w0 - h0, w1 - h1);
        }
        {
            float w0 = __ldg(W2 + (size_t)l * D * D + k0 * D + n);
            float w1 = __ldg(W2 + (size_t)l * D * D + (k0 + 1) * D + n);
            float h0 = bf_hi(w0), h1 = bf_hi(w1);
            g_w2p[l][chunk][0][n][kpi] = pack_bf2(h0, h1);
            g_w2p[l][chunk][1][n][kpi] = pack_bf2(w0 - h0, w1 - h1);
        }
        return;
    }
    r -= R_W;
    if (r < R_W3) {
        int n = r & 63;
        int kp = r >> 6;
        int k0 = kp * 2;
        int chunk = k0 >> 4;
        int kpi = (k0 & 15) >> 1;
        float w0 = __ldg(Wout + k0 * OD + n);
        float w1 = __ldg(Wout + (k0 + 1) * OD + n);
        g_w3p[chunk][n][kpi] = pack_h2(w0, w1);
        return;
    }
    r -= R_W3;
    if (r < R_ST) { ((float*)g_stats)[r] = 0.f; return; }
    r -= R_ST;
    if (r == 0) g_off[0] = 0;
}

// --- scan1: per-block inclusive scan over 4-bucket counts ---
__global__ void scan1_kernel() {
    int b = blockIdx.x, tid = threadIdx.x;
    int i = b * 256 + tid;
    int c0 = 0, c1 = 0, c2 = 0, c3 = 0;
    if (i < NN) {
        c0 = g_cnt[0][i]; c1 = g_cnt[1][i];
        c2 = g_cnt[2][i]; c3 = g_cnt[3][i];
    }
    int v = c0 + c1 + c2 + c3;
    int lane = tid & 31, w = tid >> 5;
    int x = v;
#pragma unroll
    for (int o = 1; o < 32; o <<= 1) {
        int t = __shfl_up_sync(0xffffffffu, x, o);
        if (lane >= o) x += t;
    }
    __shared__ int wsum[8];
    if (lane == 31) wsum[w] = x;
    __syncthreads();
    if (w == 0 && lane < 8) {
        int y = wsum[lane];
#pragma unroll
        for (int o = 1; o < 8; o <<= 1) {
            int t = __shfl_up_sync(0xffu, y, o);
            if (lane >= o) y += t;
        }
        wsum[lane] = y;
    }
    __syncthreads();
    int incl = x + (w > 0 ? wsum[w - 1] : 0);
    if (i < NN) {
        int excl = incl - v;
        g_off[i + 1] = incl;
        g_cur[0][i] = excl;
        g_cur[1][i] = excl + c0;
        g_cur[2][i] = excl + c0 + c1;
        g_cur[3][i] = excl + c0 + c1 + c2;
    }
    if (tid == 255) g_bsum[b] = incl;
}

// --- scan23 (merged): each block computes its own base, applies it ---
__global__ void scan23_kernel() {
    __shared__ int sbase;
    int b = blockIdx.x, tid = threadIdx.x;
    if (tid < 32) {
        int part = 0;
        for (int j = tid; j < b; j += 32) part += g_bsum[j];
#pragma unroll
        for (int o = 16; o > 0; o >>= 1)
            part += __shfl_xor_sync(0xffffffffu, part, o);
        if (tid == 0) sbase = part;
    }
    __syncthreads();
    int base = sbase;
    int i = b * 256 + tid;
    if (i < NN) {
        g_off[i + 1] += base;
        g_cur[0][i] += base;
        g_cur[1][i] += base;
        g_cur[2][i] += base;
        g_cur[3][i] += base;
    }
}

// fill + re-zero g_cnt for the NEXT call
__global__ void csr_fill_kernel(const int* __restrict__ src,
                                const int* __restrict__ dst) {
    int i = blockIdx.x * blockDim.x + threadIdx.x;
    if (i < NN) {
        g_cnt[0][i] = 0; g_cnt[1][i] = 0;
        g_cnt[2][i] = 0; g_cnt[3][i] = 0;
    }
    if (i >= NE / 4) return;
    int b = bucket_of(i);
    int4 s = __ldg((const int4*)src + i);
    int4 d = __ldg((const int4*)dst + i);
    int p0 = atomicAdd(&g_cur[b][d.x], 1);
    int p1 = atomicAdd(&g_cur[b][d.y], 1);
    int p2 = atomicAdd(&g_cur[b][d.z], 1);
    int p3 = atomicAdd(&g_cur[b][d.w], 1);
    g_csrc[p0] = s.x;
    g_csrc[p1] = s.y;
    g_csrc[p2] = s.z;
    g_csrc[p3] = s.w;
}

// ---------------- gather (fp16 h, uint2 8-deep — proven best) ----------------
__global__ void __launch_bounds__(256) gather_kernel(const float* __restrict__ eps,
                                                     int layer) {
    int node = blockIdx.x * 8 + (threadIdx.x >> 5);
    if (node >= NN) return;
    int lane = threadIdx.x & 31;
    float oe = 1.0f + __ldg(eps + layer);

    int beg = g_off[node];
    int end = g_off[node + 1];

    const __half* hb = g_hh;
    float4 hv = h4_to_f4(*(const uint2*)(hb + (size_t)node * D + lane * 4));
    float4 acc;
    acc.x = oe * hv.x; acc.y = oe * hv.y; acc.z = oe * hv.z; acc.w = oe * hv.w;

    int i = beg;
    for (; i + 7 < end; i += 8) {
        uint2 u[8];
#pragma unroll
        for (int j = 0; j < 8; j++) {
            int s = __ldg(g_csrc + i + j);
            u[j] = *(const uint2*)(hb + (size_t)s * D + lane * 4);
        }
#pragma unroll
        for (int j = 0; j < 8; j++) {
            float4 v = h4_to_f4(u[j]);
            acc.x += v.x; acc.y += v.y; acc.z += v.z; acc.w += v.w;
        }
    }
    for (; i + 3 < end; i += 4) {
        uint2 u[4];
#pragma unroll
        for (int j = 0; j < 4; j++) {
            int s = __ldg(g_csrc + i + j);
            u[j] = *(const uint2*)(hb + (size_t)s * D + lane * 4);
        }
#pragma unroll
        for (int j = 0; j < 4; j++) {
            float4 v = h4_to_f4(u[j]);
            acc.x += v.x; acc.y += v.y; acc.z += v.z; acc.w += v.w;
        }
    }
    for (; i < end; i++) {
        int s = __ldg(g_csrc + i);
        float4 v = h4_to_f4(*(const uint2*)(hb + (size_t)s * D + lane * 4));
        acc.x += v.x; acc.y += v.y; acc.z += v.z; acc.w += v.w;
    }
    *(float4*)(g_xin + (size_t)node * D + lane * 4) = acc;
}

// =====================================================================
// Split-bf16 tensor-core GEMM core.
// =====================================================================

struct SmemGemm {
    unsigned A[2][2][64 * 8];    // [buf][hi/lo][m*8 + kpair]  (8KB)
    unsigned B[2][2][128 * 8];   // [buf][hi/lo][n*8 + kpair]  (16KB)
};

// ---------------- GEMM1: x = xin @ W1 + b1, + BN stats ----------------
__global__ void __launch_bounds__(256) gemm1_tc_kernel(const float* __restrict__ b1,
                                                       int layer) {
    __shared__ SmemGemm sm;
    __shared__ float SredS[128], SredQ[128];

    int tid = threadIdx.x;
    int lane = tid & 31;
    int wid = tid >> 5;
    int wm = wid & 3;
    int wn = wid >> 2;
    int m0 = blockIdx.x * 64;

    if (tid < 128) { SredS[tid] = 0.f; SredQ[tid] = 0.f; }

    int lm = tid >> 2;
    int lq = (tid & 3);
    int gm_ld = m0 + lm;
    const unsigned* Wc = &g_w1p[layer][0][0][0][0];

    // prologue: chunk 0
    {
        float4 v = make_float4(0.f, 0.f, 0.f, 0.f);
        if (gm_ld < NN) v = *(const float4*)(g_xin + (size_t)gm_ld * D + lq * 4);
        unsigned hi[2], lo[2];
        split4(v, hi, lo);
        sm.A[0][0][lm * 8 + lq * 2] = hi[0];
        sm.A[0][0][lm * 8 + lq * 2 + 1] = hi[1];
        sm.A[0][1][lm * 8 + lq * 2] = lo[0];
        sm.A[0][1][lm * 8 + lq * 2 + 1] = lo[1];
        const uint4* Wg = (const uint4*)Wc;
        uint4 wh = Wg[tid], wl = Wg[tid + 256];
        ((uint4*)sm.B[0][0])[tid] = wh;
        ((uint4*)sm.B[0][1])[tid] = wl;
    }
    __syncthreads();

    float d[8][4];
#pragma unroll
    for (int nt = 0; nt < 8; nt++)
#pragma unroll
        for (int c = 0; c < 4; c++) d[nt][c] = 0.f;

    int kq = lane & 3;
    int gr = lane >> 2;
    int ca = wm * 16 + gr;

#pragma unroll
    for (int kk = 0; kk < 8; kk++) {
        const int cur = kk & 1;
        unsigned nah[2], nal[2];
        uint4 nwh, nwl;
        if (kk < 7) {
            float4 v = make_float4(0.f, 0.f, 0.f, 0.f);
            if (gm_ld < NN)
                v = *(const float4*)(g_xin + (size_t)gm_ld * D + (kk + 1) * 16 + lq * 4);
            split4(v, nah, nal);
            const uint4* Wg = (const uint4*)(Wc + (kk + 1) * 2048);
            nwh = Wg[tid]; nwl = Wg[tid + 256];
        }
        unsigned ah[4], al[4];
        ah[0] = sm.A[cur][0][ca * 8 + kq];
        ah[1] = sm.A[cur][0][(ca + 8) * 8 + kq];
        ah[2] = sm.A[cur][0][ca * 8 + kq + 4];
        ah[3] = sm.A[cur][0][(ca + 8) * 8 + kq + 4];
        al[0] = sm.A[cur][1][ca * 8 + kq];
        al[1] = sm.A[cur][1][(ca + 8) * 8 + kq];
        al[2] = sm.A[cur][1][ca * 8 + kq + 4];
        al[3] = sm.A[cur][1][(ca + 8) * 8 + kq + 4];
#pragma unroll
        for (int nt = 0; nt < 8; nt++) {
            int cb = wn * 64 + nt * 8 + gr;
            unsigned bh0 = sm.B[cur][0][cb * 8 + kq];
            unsigned bh1 = sm.B[cur][0][cb * 8 + kq + 4];
            unsigned bl0 = sm.B[cur][1][cb * 8 + kq];
            unsigned bl1 = sm.B[cur][1][cb * 8 + kq + 4];
            mma_bf16(d[nt], ah, bh0, bh1);
            mma_bf16(d[nt], ah, bl0, bl1);
            mma_bf16(d[nt], al, bh0, bh1);
        }
        if (kk < 7) {
            const int nxt = cur ^ 1;
            sm.A[nxt][0][lm * 8 + lq * 2] = nah[0];
            sm.A[nxt][0][lm * 8 + lq * 2 + 1] = nah[1];
            sm.A[nxt][1][lm * 8 + lq * 2] = nal[0];
            sm.A[nxt][1][lm * 8 + lq * 2 + 1] = nal[1];
            ((uint4*)sm.B[nxt][0])[tid] = nwh;
            ((uint4*)sm.B[nxt][1])[tid] = nwl;
            __syncthreads();
        }
    }

    // epilogue: bias, store x, BN stats
    int r0 = m0 + wm * 16 + gr;
    int r1 = r0 + 8;
    bool v0r = (r0 < NN), v1r = (r1 < NN);
#pragma unroll
    for (int nt = 0; nt < 8; nt++) {
        int c0 = wn * 64 + nt * 8 + 2 * kq;
        float bb0 = __ldg(b1 + (size_t)layer * D + c0);
        float bb1 = __ldg(b1 + (size_t)layer * D + c0 + 1);
        float x0 = d[nt][0] + bb0, x1 = d[nt][1] + bb1;
        float x2 = d[nt][2] + bb0, x3 = d[nt][3] + bb1;
        if (v0r) *(float2*)(g_x + (size_t)r0 * D + c0) = make_float2(x0, x1);
        if (v1r) *(float2*)(g_x + (size_t)r1 * D + c0) = make_float2(x2, x3);
        float sc0 = (v0r ? x0 : 0.f) + (v1r ? x2 : 0.f);
        float sc1 = (v0r ? x1 : 0.f) + (v1r ? x3 : 0.f);
        float qc0 = (v0r ? x0 * x0 : 0.f) + (v1r ? x2 * x2 : 0.f);
        float qc1 = (v0r ? x1 * x1 : 0.f) + (v1r ? x3 * x3 : 0.f);
#pragma unroll
        for (int o = 4; o <= 16; o <<= 1) {
            sc0 += __shfl_xor_sync(0xffffffffu, sc0, o);
            sc1 += __shfl_xor_sync(0xffffffffu, sc1, o);
            qc0 += __shfl_xor_sync(0xffffffffu, qc0, o);
            qc1 += __shfl_xor_sync(0xffffffffu, qc1, o);
        }
        if (gr == 0) {
            atomicAdd(&SredS[c0], sc0);
            atomicAdd(&SredS[c0 + 1], sc1);
            atomicAdd(&SredQ[c0], qc0);
            atomicAdd(&SredQ[c0 + 1], qc1);
        }
    }
    __syncthreads();
    if (tid < 128) {
        atomicAdd(&g_stats[layer][tid], SredS[tid]);
        atomicAdd(&g_stats[layer][D + tid], SredQ[tid]);
    }
}

// ---------------- GEMM2: h = relu( relu(BN(x)) @ W2 + b2 ) ----------------
// layers 0,1: h -> g_hh (fp16). layer 2: fused GEMM3, writes `out` directly.
__global__ void __launch_bounds__(256) gemm2_tc_kernel(const float* __restrict__ b2,
                                                       const float* __restrict__ gamma,
                                                       const float* __restrict__ beta,
                                                       const float* __restrict__ bout,
                                                       float* __restrict__ out,
                                                       int layer) {
    __shared__ SmemGemm sm;
    __shared__ float s_sc[128], s_sh[128];

    int tid = threadIdx.x;
    int lane = tid & 31;
    int wid = tid >> 5;
    int wm = wid & 3;
    int wn = wid >> 2;
    int m0 = blockIdx.x * 64;

    if (tid < 128) {
        float inv = 1.0f / (float)NN;
        float mu = g_stats[layer][tid] * inv;
        float var = g_stats[layer][D + tid] * inv - mu * mu;
        float rs = rsqrtf(var + 1e-5f);
        float sc = rs * __ldg(gamma + (size_t)layer * D + tid);
        s_sc[tid] = sc;
        s_sh[tid] = __ldg(beta + (size_t)layer * D + tid) - mu * sc;
    }
    __syncthreads();

    int lm = tid >> 2;
    int lq = (tid & 3);
    int gm_ld = m0 + lm;
    const unsigned* Wc = &g_w2p[layer][0][0][0][0];

    {
        float4 v = make_float4(0.f, 0.f, 0.f, 0.f);
        if (gm_ld < NN) {
            float4 xv = *(const float4*)(g_x + (size_t)gm_ld * D + lq * 4);
            int c = lq * 4;
            v.x = fmaxf(fmaf(xv.x, s_sc[c + 0], s_sh[c + 0]), 0.f);
            v.y = fmaxf(fmaf(xv.y, s_sc[c + 1], s_sh[c + 1]), 0.f);
            v.z = fmaxf(fmaf(xv.z, s_sc[c + 2], s_sh[c + 2]), 0.f);
            v.w = fmaxf(fmaf(xv.w, s_sc[c + 3], s_sh[c + 3]), 0.f);
        }
        unsigned hi[2], lo[2];
        split4(v, hi, lo);
        sm.A[0][0][lm * 8 + lq * 2] = hi[0];
        sm.A[0][0][lm * 8 + lq * 2 + 1] = hi[1];
        sm.A[0][1][lm * 8 + lq * 2] = lo[0];
        sm.A[0][1][lm * 8 + lq * 2 + 1] = lo[1];
        const uint4* Wg = (const uint4*)Wc;
        uint4 wh = Wg[tid], wl = Wg[tid + 256];
        ((uint4*)sm.B[0][0])[tid] = wh;
        ((uint4*)sm.B[0][1])[tid] = wl;
    }
    __syncthreads();

    float d[8][4];
#pragma unroll
    for (int nt = 0; nt < 8; nt++)
#pragma unroll
        for (int c = 0; c < 4; c++) d[nt][c] = 0.f;

    int kq = lane & 3;
    int gr = lane >> 2;
    int ca = wm * 16 + gr;

#pragma unroll
    for (int kk = 0; kk < 8; kk++) {
        const int cur = kk & 1;
        unsigned nah[2], nal[2];
        uint4 nwh, nwl;
        if (kk < 7) {
            float4 v = make_float4(0.f, 0.f, 0.f, 0.f);
            int kc = (kk + 1) * 16;
            if (gm_ld < NN) {
                float4 xv = *(const float4*)(g_x + (size_t)gm_ld * D + kc + lq * 4);
                int c = kc + lq * 4;
                v.x = fmaxf(fmaf(xv.x, s_sc[c + 0], s_sh[c + 0]), 0.f);
                v.y = fmaxf(fmaf(xv.y, s_sc[c + 1], s_sh[c + 1]), 0.f);
                v.z = fmaxf(fmaf(xv.z, s_sc[c + 2], s_sh[c + 2]), 0.f);
                v.w = fmaxf(fmaf(xv.w, s_sc[c + 3], s_sh[c + 3]), 0.f);
            }
            split4(v, nah, nal);
            const uint4* Wg = (const uint4*)(Wc + (kk + 1) * 2048);
            nwh = Wg[tid]; nwl = Wg[tid + 256];
        }
        unsigned ah[4], al[4];
        ah[0] = sm.A[cur][0][ca * 8 + kq];
        ah[1] = sm.A[cur][0][(ca + 8) * 8 + kq];
        ah[2] = sm.A[cur][0][ca * 8 + kq + 4];
        ah[3] = sm.A[cur][0][(ca + 8) * 8 + kq + 4];
        al[0] = sm.A[cur][1][ca * 8 + kq];
        al[1] = sm.A[cur][1][(ca + 8) * 8 + kq];
        al[2] = sm.A[cur][1][ca * 8 + kq + 4];
        al[3] = sm.A[cur][1][(ca + 8) * 8 + kq + 4];
#pragma unroll
        for (int nt = 0; nt < 8; nt++) {
            int cb = wn * 64 + nt * 8 + gr;
            unsigned bh0 = sm.B[cur][0][cb * 8 + kq];
            unsigned bh1 = sm.B[cur][0][cb * 8 + kq + 4];
            unsigned bl0 = sm.B[cur][1][cb * 8 + kq];
            unsigned bl1 = sm.B[cur][1][cb * 8 + kq + 4];
            mma_bf16(d[nt], ah, bh0, bh1);
            mma_bf16(d[nt], ah, bl0, bl1);
            mma_bf16(d[nt], al, bh0, bh1);
        }
        if (kk < 7) {
            const int nxt = cur ^ 1;
            sm.A[nxt][0][lm * 8 + lq * 2] = nah[0];
            sm.A[nxt][0][lm * 8 + lq * 2 + 1] = nah[1];
            sm.A[nxt][1][lm * 8 + lq * 2] = nal[0];
            sm.A[nxt][1][lm * 8 + lq * 2 + 1] = nal[1];
            ((uint4*)sm.B[nxt][0])[tid] = nwh;
            ((uint4*)sm.B[nxt][1])[tid] = nwl;
            __syncthreads();
        }
    }

    int r0 = m0 + wm * 16 + gr;
    int r1 = r0 + 8;

    if (layer < 2) {
        // epilogue: relu(d + b2) -> g_hh (fp16)
#pragma unroll
        for (int nt = 0; nt < 8; nt++) {
            int c0 = wn * 64 + nt * 8 + 2 * kq;
            float bb0 = __ldg(b2 + (size_t)layer * D + c0);
            float bb1 = __ldg(b2 + (size_t)layer * D + c0 + 1);
            if (r0 < NN) {
                *(__half2*)(g_hh + (size_t)r0 * D + c0) =
                    __floats2half2_rn(fmaxf(d[nt][0] + bb0, 0.f),
                                      fmaxf(d[nt][1] + bb1, 0.f));
            }
            if (r1 < NN) {
                *(__half2*)(g_hh + (size_t)r1 * D + c0) =
                    __floats2half2_rn(fmaxf(d[nt][2] + bb0, 0.f),
                                      fmaxf(d[nt][3] + bb1, 0.f));
            }
        }
        return;
    }

    // ---- layer 2: fused GEMM3: out = relu(d+b2) @ Wout + bout ----
    // Pack fp16 h tile into sm.B reinterpreted as sh_h[chunk(8)][m(64)][kpair(8)].
    __syncthreads();   // all mma reads of sm.B done
    unsigned* sh_h = &sm.B[0][0][0];    // 4096 uints = 16KB
#pragma unroll
    for (int nt = 0; nt < 8; nt++) {
        int c0 = wn * 64 + nt * 8 + 2 * kq;
        float bb0 = __ldg(b2 + (size_t)layer * D + c0);
        float bb1 = __ldg(b2 + (size_t)layer * D + c0 + 1);
        int chunk = c0 >> 4;
        int kpi = (c0 & 15) >> 1;
        int rl0 = wm * 16 + gr;
        sh_h[(chunk * 64 + rl0) * 8 + kpi] =
            pack_h2(fmaxf(d[nt][0] + bb0, 0.f), fmaxf(d[nt][1] + bb1, 0.f));
        sh_h[(chunk * 64 + rl0 + 8) * 8 + kpi] =
            pack_h2(fmaxf(d[nt][2] + bb0, 0.f), fmaxf(d[nt][3] + bb1, 0.f));
    }
    __syncthreads();

    unsigned* sw = &sm.A[0][0][0];      // 512 uints per chunk
    float d3[4][4];
#pragma unroll
    for (int nt = 0; nt < 4; nt++)
#pragma unroll
        for (int c = 0; c < 4; c++) d3[nt][c] = 0.f;

#pragma unroll
    for (int kk = 0; kk < 8; kk++) {
        if (tid < 128)
            ((uint4*)sw)[tid] = ((const uint4*)&g_w3p[kk][0][0])[tid];
        __syncthreads();
        unsigned a[4];
        a[0] = sh_h[(kk * 64 + ca) * 8 + kq];
        a[1] = sh_h[(kk * 64 + ca + 8) * 8 + kq];
        a[2] = sh_h[(kk * 64 + ca) * 8 + kq + 4];
        a[3] = sh_h[(kk * 64 + ca + 8) * 8 + kq + 4];
#pragma unroll
        for (int nt = 0; nt < 4; nt++) {
            int cb = wn * 32 + nt * 8 + gr;
            unsigned b0 = sw[cb * 8 + kq];
            unsigned b1 = sw[cb * 8 + kq + 4];
            mma_f16(d3[nt], a, b0, b1);
        }
        __syncthreads();
    }

#pragma unroll
    for (int nt = 0; nt < 4; nt++) {
        int c0 = wn * 32 + nt * 8 + 2 * kq;
        float bb0 = __ldg(bout + c0);
        float bb1 = __ldg(bout + c0 + 1);
        if (r0 < NN)
            *(float2*)(out + (size_t)r0 * OD + c0) =
                make_float2(d3[nt][0] + bb0, d3[nt][1] + bb1);
        if (r1 < NN)
            *(float2*)(out + (size_t)r1 * OD + c0) =
                make_float2(d3[nt][2] + bb0, d3[nt][3] + bb1);
    }
}

// ---------------- launch ----------------
extern "C" void kernel_launch(void* const* d_in, const int* in_sizes, int n_in,
                              void* d_out, int out_size) {
    const float* node_feat = (const float*)d_in[0];
    const int*   src       = (const int*)d_in[1];
    const int*   dst       = (const int*)d_in[2];
    const float* W1        = (const float*)d_in[3];
    const float* b1        = (const float*)d_in[4];
    const float* gamma     = (const float*)d_in[5];
    const float* beta      = (const float*)d_in[6];
    const float* W2        = (const float*)d_in[7];
    const float* b2        = (const float*)d_in[8];
    const float* eps       = (const float*)d_in[9];
    const float* Wout      = (const float*)d_in[10];
    const float* bout      = (const float*)d_in[11];
    float* out = (float*)d_out;

    const int gemm_grid  = (NN + 63) / 64;          // 782
    const int edge4_grid = (NE / 4 + 255) / 256;    // 1563
    const int gath_grid  = (NN + 7) / 8;            // 6250
    const int init_grid  = (R_TOT + 255) / 256;

    init_kernel<<<init_grid, 256>>>(node_feat, W1, W2, Wout, dst);
    scan1_kernel<<<NBLK, 256>>>();
    scan23_kernel<<<NBLK, 256>>>();
    csr_fill_kernel<<<edge4_grid, 256>>>(src, dst);

    for (int l = 0; l < NL; l++) {
        gather_kernel<<<gath_grid, 256>>>(eps, l);
        gemm1_tc_kernel<<<gemm_grid, 256>>>(b1, l);
        gemm2_tc_kernel<<<gemm_grid, 256>>>(b2, gamma, beta, bout, out, l);
    }
}